// round 16
// baseline (speedup 1.0000x reference)
#include <cuda_runtime.h>
#include <cuda_bf16.h>
#include <cuda_fp8.h>
#include <cstdint>
#include <math.h>

#define BATCH 64
#define STAGES 4    // legacy path cp.async stages
#define TSTG 5      // tc path pipeline stages
#define CSZ 2       // tc path cluster size (A multicast; 148=2*74 packs perfectly)

// Arch-feature guard: tcgen05 only exists in the arch-specific (sm_103a/sm_100a) pass.
#if defined(__CUDA_ARCH__) && (defined(__CUDA_ARCH_FEAT_SM103_ALL) || defined(__CUDA_ARCH_FEAT_SM100_ALL))
#define HAS_TC 1
#else
#define HAS_TC 0
#endif

// e4m3 bytes for integer magnitudes 0..7 (LO) and 8..15 (HI), byte i at bits 8i
#define FP8LUT_LO 0x4E4C4A4844403800ull
#define FP8LUT_HI 0x5756555453525150ull

// ---------------- scratch (device globals; 1 byte/elem both paths: fp8 e4m3 | int8) ----------------
// NOTE: device globals are zero-initialized at module load. Kernels only ever write the
// interior pixels of the padded activation buffers, so the zero borders persist across
// all graph replays — no memsets needed.
__device__ __align__(1024) char g_xs2p[(size_t)4 * BATCH * 34 * 34 * 512]; // conv2 input slices
__device__ __align__(1024) char g_zsp [(size_t)4 * BATCH * 18 * 18 * 512]; // conv3 input slices
__device__ __align__(1024) char g_ws2 [(size_t)4 * 512 * 9 * 512];         // conv2 weight slices
__device__ __align__(1024) char g_ws3 [(size_t)4 * 512 * 9 * 512];         // conv3 weight slices
__device__ __align__(128) int8_t g_wslin[4 * 10 * 512];

// ---------------- helpers ----------------
__device__ __forceinline__ int quant16(float v) {
    float r = rintf(v * 16384.0f);
    r = fminf(fmaxf(r, -32768.0f), 32767.0f);
    return (int)r;
}

__device__ __forceinline__ float acm_finish(long long sum) {
    long long q = sum >> 4;
    int rem = (int)(sum & 15);
    if (rem > 8 || (rem == 8 && (q & 1))) q += 1;
    if (q >  2147483647LL) q =  2147483647LL;
    if (q < -2147483648LL) q = -2147483648LL;
    return (float)q * 5.9604644775390625e-08f;   // * 2^-24
}

__device__ __forceinline__ float acm_combine16(const int* acc) {
    long long sum = 0;
#pragma unroll
    for (int t = 0; t < 4; t++)
#pragma unroll
        for (int s = 0; s < 4; s++) {
            int v = acc[t * 4 + s];
            v = v < -8192 ? -8192 : (v > 8191 ? 8191 : v);
            sum += ((long long)v) << (4 * (t + s));
        }
    return acm_finish(sum);
}

__device__ __forceinline__ void cp16(uint32_t dst, const void* src) {
    asm volatile("cp.async.cg.shared.global [%0], [%1], 16;\n" :: "r"(dst), "l"(src));
}
__device__ __forceinline__ void cp_commit() {
    asm volatile("cp.async.commit_group;\n" ::: "memory");
}

__device__ __forceinline__ void mma_s8(int* d, const int* a, const int* b) {
    asm volatile(
        "mma.sync.aligned.m16n8k32.row.col.s32.s8.s8.s32 "
        "{%0,%1,%2,%3}, {%4,%5,%6,%7}, {%8,%9}, {%0,%1,%2,%3};\n"
        : "+r"(d[0]), "+r"(d[1]), "+r"(d[2]), "+r"(d[3])
        : "r"(a[0]), "r"(a[1]), "r"(a[2]), "r"(a[3]), "r"(b[0]), "r"(b[1]));
}

#if HAS_TC
__device__ __forceinline__ uint32_t elect_one() {
    uint32_t pred;
    asm volatile("{\n\t.reg .pred p;\n\telect.sync _|p, 0xFFFFFFFF;\n\tselp.b32 %0, 1, 0, p;\n\t}"
                 : "=r"(pred));
    return pred;
}
__device__ __forceinline__ void mbar_init(uint32_t addr, uint32_t cnt) {
    asm volatile("mbarrier.init.shared.b64 [%0], %1;" :: "r"(addr), "r"(cnt) : "memory");
}
__device__ __forceinline__ void mbar_wait(uint32_t mbar, uint32_t parity) {
    uint32_t done = 0;
    while (!done) {
        asm volatile(
            "{\n\t.reg .pred p;\n\t"
            "mbarrier.try_wait.parity.acquire.cta.shared::cta.b64 p, [%1], %2, 0x989680;\n\t"
            "selp.b32 %0, 1, 0, p;\n\t}"
            : "=r"(done) : "r"(mbar), "r"(parity) : "memory");
    }
}
// relaxed wait: valid when all post-wait smem accesses are async-proxy (cp.async/TMA/tcgen05)
__device__ __forceinline__ void mbar_wait_rlx(uint32_t mbar, uint32_t parity) {
    uint32_t done = 0;
    while (!done) {
        asm volatile(
            "{\n\t.reg .pred p;\n\t"
            "mbarrier.try_wait.parity.relaxed.cta.shared::cta.b64 p, [%1], %2, 0x989680;\n\t"
            "selp.b32 %0, 1, 0, p;\n\t}"
            : "=r"(done) : "r"(mbar), "r"(parity) : "memory");
    }
}
// tcgen05 SS-mode fp8 (e4m3) mma, cg1, f32 accumulate, no block scales
__device__ __forceinline__ void tc_mma_f8(uint32_t d, uint64_t ad, uint64_t bd,
                                          uint32_t idesc, uint32_t en) {
    asm volatile(
        "{\n\t.reg .pred p;\n\t"
        "setp.ne.u32 p, %4, 0;\n\t"
        "tcgen05.mma.cta_group::1.kind::f8f6f4 [%0], %1, %2, %3, {%5,%5,%5,%5}, p;\n\t}"
        :: "r"(d), "l"(ad), "l"(bd), "r"(idesc), "r"(en), "r"(0u)
        : "memory");
}
// SW64 K-major smem descriptor base: layout=4, version=1, SBO=32 (512B = 8 rows x 64B), LBO=1
#define DESC64 ((4ULL << 61) | (1ULL << 46) | (32ULL << 32) | (1ULL << 16))
// idesc: dtype=F32 (1<<4), atype=E4M3, btype=E4M3, N=128 (16<<17), M=128 (8<<24)
#define MMA_IDESC_F8 0x08200010u
#endif

// ---------------- conv1: float conv 3->512 (3x3, s1, p1) + fused slice quantize ----------------
// (proven round-14 version: 148us) Slice writes staged through smem -> 64B-contiguous u64 stores.
__global__ void conv1_kernel(const float* __restrict__ x, const float* __restrict__ w1,
                             float* __restrict__ y, void* __restrict__ xs_raw) {
    int h = blockIdx.y;
    int b = blockIdx.z;
    int o0 = blockIdx.x * 64;
    __shared__ float sx[3][3][34];
    __shared__ float sw[64 * 27];
    __shared__ unsigned long long stg[4][8][32];   // [s][o-group][w]
    int tid = threadIdx.x;
    for (int i = tid; i < 64 * 27; i += 256)
        sw[i] = w1[(o0 + i / 27) * 27 + (i % 27)];
    for (int i = tid; i < 306; i += 256) {
        int c = i / 102, rem = i % 102, dh = rem / 34, j = rem % 34;
        int ih = h - 1 + dh, iw = j - 1;
        float v = 0.f;
        if (ih >= 0 && ih < 32 && iw >= 0 && iw < 32)
            v = x[((b * 3 + c) * 32 + ih) * 32 + iw];
        sx[c][dh][j] = v;
    }
    __syncthreads();
    int w = tid & 31, og = tid >> 5;
    float acc[8];
#pragma unroll
    for (int i = 0; i < 8; i++) acc[i] = 0.f;
#pragma unroll
    for (int c = 0; c < 3; c++)
#pragma unroll
        for (int kh = 0; kh < 3; kh++)
#pragma unroll
            for (int kw = 0; kw < 3; kw++) {
                float xv = sx[c][kh][w + kw];
#pragma unroll
                for (int oo = 0; oo < 8; oo++)
                    acc[oo] += xv * sw[(og * 8 + oo) * 27 + c * 9 + kh * 3 + kw];
            }
    // y writes (coalesced across w within each warp)
#pragma unroll
    for (int oo = 0; oo < 8; oo++) {
        int o = o0 + og * 8 + oo;
        y[(((size_t)b * 512 + o) * 32 + h) * 32 + w] = acc[oo];
    }
    // pack 8 channel-bytes per plane into u64 and stage
    unsigned long long pk[4] = {0ull, 0ull, 0ull, 0ull};
#pragma unroll
    for (int oo = 0; oo < 8; oo++) {
        int qi = quant16(acc[oo]);
        int sg = (qi > 0) - (qi < 0);
        int mag = qi < 0 ? -qi : qi;
#pragma unroll
        for (int s = 0; s < 4; s++) {
            int v = sg * ((mag >> (4 * s)) & 15);
#if HAS_TC
            unsigned char byte = (unsigned char)__nv_cvt_float_to_fp8((float)v, __NV_SATFINITE, __NV_E4M3);
#else
            unsigned char byte = (unsigned char)(int8_t)v;
#endif
            pk[s] |= ((unsigned long long)byte) << (8 * oo);
        }
    }
#pragma unroll
    for (int s = 0; s < 4; s++) stg[s][og][w] = pk[s];
    __syncthreads();
    // write out: thread (ow = tid>>3, ogp = tid&7) -> 64B-contiguous runs per w
    int ow = tid >> 3, ogp = tid & 7;
    const size_t plane = (size_t)BATCH * 34 * 34 * 512;
    size_t pixbase = (((size_t)(b * 34 + h + 1)) * 34 + (ow + 1)) * 512 + o0 + ogp * 8;
    char* xs = (char*)xs_raw;
#pragma unroll
    for (int s = 0; s < 4; s++)
        *(unsigned long long*)(xs + s * plane + pixbase) = stg[s][ogp][ow];
}

// ---------------- weight prep ----------------
// tc path: blocked+preswizzled: [mt(4)][chunk(72)][row(512)=t*128+ol][64B], 32KB/chunk
// legacy : [t][o][r*512+c]
__global__ void wprep_conv_kernel(const float* __restrict__ w, void* __restrict__ ws_raw) {
    int idx = blockIdx.x * blockDim.x + threadIdx.x;
    if (idx >= 512 * 9 * 512) return;
    int c = idx & 511;
    int r = (idx >> 9) % 9;
    int o = idx / (512 * 9);
    float v = w[((size_t)o * 512 + c) * 9 + r];
    int qi = quant16(v);
    int sg = (qi > 0) - (qi < 0);
    int mag = qi < 0 ? -qi : qi;
#if HAS_TC
    __nv_fp8_e4m3* ws = (__nv_fp8_e4m3*)ws_raw;
    int mt = o >> 7, ol = o & 127;
    int chunk = r * 8 + (c >> 6);
    int j = (c >> 4) & 3;
    int byte = c & 15;
#pragma unroll
    for (int t = 0; t < 4; t++) {
        int row = t * 128 + ol;
        int sw = (row >> 1) & 3;
        size_t dst = (((size_t)(mt * 72 + chunk) * 512 + row) * 64) + ((j ^ sw) * 16) + byte;
        ws[dst] = __nv_fp8_e4m3((float)(sg * ((mag >> (4 * t)) & 15)));
    }
#else
    int8_t* ws = (int8_t*)ws_raw;
    size_t plane = (size_t)512 * 4608;
#pragma unroll
    for (int t = 0; t < 4; t++)
        ws[(size_t)t * plane + (size_t)o * 4608 + r * 512 + c] =
            (int8_t)(sg * ((mag >> (4 * t)) & 15));
#endif
}

__global__ void wprep_lin_kernel(const float* __restrict__ w, int8_t* __restrict__ ws) {
    int idx = blockIdx.x * blockDim.x + threadIdx.x;
    if (idx >= 10 * 512) return;
    int k = idx & 511, o = idx >> 9;
    int qi = quant16(w[o * 512 + k]);
    int sg = (qi > 0) - (qi < 0);
    int mag = qi < 0 ? -qi : qi;
#pragma unroll
    for (int t = 0; t < 4; t++)
        ws[(t * 10 + o) * 512 + k] = (int8_t)(sg * ((mag >> (4 * t)) & 15));
}

// ---------------- bit-sliced MVM conv: warp-specialized tcgen05 fp8 + A multicast | legacy ----------------
// tc grid: (N/32, 4), TSTG-stage pipeline. Legacy path never executes on sm_103a.
__global__ void __launch_bounds__(256, 1) __cluster_dims__(CSZ, 1, 1) mvm_conv_kernel(
    const void* __restrict__ xs_raw, const void* __restrict__ ws_raw,
    float* __restrict__ outz, void* __restrict__ zsl_raw, int OH, int OW) {

    extern __shared__ __align__(1024) char dsm[];
    const int B = BATCH;
    const int IHP = 2 * OH + 2, IWP = 2 * OW + 2;
    const int tid = threadIdx.x;
    const int lane = tid & 31, wid = tid >> 5;

#if HAS_TC
    // ================= tcgen05 fp8, warp-specialized producer/consumer =================
    // Accumulators: 4 TMEM regions (one per t-slice), each M=128 x N=128 where the
    // N index is s*32+px (B smem rows are s*32+px). A read once per (t,k): 32KB/chunk.
    const uint8_t* xs = (const uint8_t*)xs_raw;
    const uint8_t* ws = (const uint8_t*)ws_raw;
    __nv_fp8_e4m3* zsl = (__nv_fp8_e4m3*)zsl_raw;

    const int n0 = blockIdx.x * 32;
    const int mt = blockIdx.y;
    const int m0 = mt * 128;
    uint32_t rank;
    asm("mov.u32 %0, %%cluster_ctarank;" : "=r"(rank));

    const uint32_t sbase = (uint32_t)__cvta_generic_to_shared(dsm);
    const uint32_t mb_done  = sbase + 16;    // TSTG x 8B, count 1 (mma commit)
    const uint32_t mb_full  = sbase + 16 + TSTG * 8;        // count 129
    const uint32_t mb_empty = sbase + 16 + 2 * TSTG * 8;    // count CSZ
    const int OFF_A = 1024;                  // TSTG x 32KB (512 rows x 64B, row = t*128+ol)
    const int OFF_B = 1024 + TSTG * 32768;   // TSTG x 8KB  (128 rows x 64B, row = s*32+px)

    if (tid == 0) {
#pragma unroll
        for (int i = 0; i < TSTG; i++) {
            mbar_init(mb_done  + i * 8, 1);
            mbar_init(mb_full  + i * 8, 129);
            mbar_init(mb_empty + i * 8, CSZ);
        }
    }
    __syncthreads();
    // all cluster CTAs' barriers initialized before any multicast targets them
    asm volatile("barrier.cluster.arrive.aligned;" ::: "memory");
    asm volatile("barrier.cluster.wait.aligned;" ::: "memory");

    uint32_t tmem = 0;

    if (wid == 0) {
        // ---------------- consumer warp ----------------
        asm volatile("tcgen05.alloc.cta_group::1.sync.aligned.shared::cta.b32 [%0], %1;"
                     :: "r"(sbase), "r"(512u) : "memory");
        asm volatile("ld.shared.b32 %0, [%1];" : "=r"(tmem) : "r"(sbase));

#pragma unroll 1
        for (int c = 0; c < 72; c++) {
            const int buf = c % TSTG;
            const uint32_t par = (uint32_t)((c / TSTG) & 1);
            mbar_wait_rlx(mb_full + buf * 8, par);  // A (tx) + B (128 arrives); MMA = async proxy
            if (elect_one()) {
                asm volatile("tcgen05.fence::after_thread_sync;" ::: "memory");
                uint64_t aD0 = DESC64 | (uint64_t)(((sbase + OFF_A + buf * 32768) >> 4) & 0x3FFF);
                uint64_t bD0 = DESC64 | (uint64_t)(((sbase + OFF_B + buf * 8192) >> 4) & 0x3FFF);
#pragma unroll
                for (int t = 0; t < 4; t++)
#pragma unroll
                    for (int k = 0; k < 2; k++) {   // K=32 fp8 per dispatch, N=128
                        uint64_t ad = aD0 + (uint64_t)(t * 512 + k * 2);
                        uint64_t bd = bD0 + (uint64_t)(k * 2);
                        uint32_t d = tmem + t * 128;
                        tc_mma_f8(d, ad, bd, MMA_IDESC_F8, (uint32_t)(c + k));
                    }
                asm volatile(
                    "tcgen05.commit.cta_group::1.mbarrier::arrive::one.shared::cluster.b64 [%0];"
                    :: "r"(mb_done + buf * 8) : "memory");
            }
        }
    } else if (tid >= 128) {
        // ---------------- producer warps (4..7) ----------------
        const int px = tid & 31;               // pixel within n-tile
        const int n = n0 + px;
        const int bb = n / (OH * OW);
        const int rr = n - bb * (OH * OW);
        const int oh = rr / OW, ow = rr - oh * OW;
        const size_t sPlane = (size_t)B * IHP * IWP * 512;
        const uint8_t* bsrc0 =
            xs + (size_t)((tid - 128) >> 5) * sPlane +
            ((size_t)(bb * IHP + 2 * oh) * IWP + 2 * ow) * 512;
        const uint32_t bdst0 = sbase + OFF_B + (tid - 128) * 64;
        const int bsw = (tid >> 1) & 3;

        auto fillA = [&](int c2) {
            const int buf2 = c2 % TSTG;
            const uint8_t* src = ws + ((size_t)(mt * 72 + c2) * 32768) + (size_t)rank * 16384;
            const uint32_t dst = sbase + OFF_A + buf2 * 32768 + rank * 16384;
            const uint32_t fb = mb_full + buf2 * 8;
            asm volatile("mbarrier.arrive.expect_tx.shared.b64 _, [%0], %1;"
                         :: "r"(fb), "r"(32768u) : "memory");
            asm volatile(
                "cp.async.bulk.shared::cluster.global.mbarrier::complete_tx::bytes.multicast::cluster "
                "[%0], [%1], %2, [%3], %4;"
                :: "r"(dst), "l"(src), "r"(16384u), "r"(fb), "h"((unsigned short)0x3)
                : "memory");
        };
        auto fillB = [&](int c2) {
            const int buf2 = c2 % TSTG;
            const int r = c2 >> 3, cc = c2 & 7;
            int kh = r / 3, kw = r - 3 * kh;
            const uint8_t* src = bsrc0 + (size_t)(kh * IWP + kw) * 512 + cc * 64;
            uint32_t dst = bdst0 + buf2 * 8192;
#pragma unroll
            for (int j = 0; j < 4; j++) cp16(dst + ((j ^ bsw) * 16), src + j * 16);
            // hardware arrival on full when this thread's prior cp.asyncs land
            asm volatile("cp.async.mbarrier.arrive.noinc.shared::cta.b64 [%0];"
                         :: "r"(mb_full + buf2 * 8) : "memory");
        };

        // prologue: stages 0..TSTG-2
#pragma unroll
        for (int ps = 0; ps < TSTG - 1; ps++) {
            if (tid == 128) fillA(ps);
            fillB(ps);
        }

#pragma unroll 1
        for (int c = 0; c < 72; c++) {
            if (c >= 1) {
                const int pb = (c - 1) % TSTG;
                const uint32_t pp = (uint32_t)(((c - 1) / TSTG) & 1);
                mbar_wait_rlx(mb_done + pb * 8, pp);   // local mma(c-1) drained
                if (tid == 129) {                      // announce buf free to all peers
#pragma unroll
                    for (int pr = 0; pr < CSZ; pr++) {
                        asm volatile(
                            "{\n\t.reg .b32 ra;\n\t"
                            "mapa.shared::cluster.u32 ra, %0, %1;\n\t"
                            "mbarrier.arrive.shared::cluster.b64 _, [ra];\n\t}"
                            :: "r"(mb_empty + pb * 8), "r"(pr) : "memory");
                    }
                }
                if (tid == 128)
                    mbar_wait_rlx(mb_empty + pb * 8, pp);  // all cluster CTAs done with buf
            }
            if (c + TSTG - 1 < 72) {
                if (tid == 128) fillA(c + TSTG - 1);
                fillB(c + TSTG - 1);
            }
        }
    }
    // warps 1-3 idle until epilogue

    __syncthreads();
    // final mma completion: buffer b last used at use-index u_max(b); wait parity u_max&1.
    // 72 chunks, TSTG=5: buffers 0,1 -> u_max=14 (parity 0); buffers 2,3,4 -> u_max=13 (parity 1).
#pragma unroll
    for (int i = 0; i < TSTG; i++) {
        const uint32_t fin_par = (uint32_t)((((72 - 1 - i) / TSTG)) & 1);
        mbar_wait(mb_done + i * 8, fin_par);
    }
    asm volatile("tcgen05.fence::after_thread_sync;" ::: "memory");
    asm volatile("ld.shared.b32 %0, [%1];" : "=r"(tmem) : "r"(sbase));

    // epilogue: warp w handles rows (w&3)*32+lane, col-groups (w>>2)*4 .. +3
    // acc(t,s,px) lives at TMEM col t*128 + s*32 + px
    const int o = m0 + (wid & 3) * 32 + lane;
    const int cg0 = (wid >> 2) * 4;
#pragma unroll 1
    for (int cgi = 0; cgi < 4; cgi++) {
        const int cg = cg0 + cgi;
        long long sum[4] = {0, 0, 0, 0};
#pragma unroll
        for (int ts = 0; ts < 16; ts++) {
            const int t = ts >> 2, s = ts & 3;
            uint32_t r0, r1, r2, r3;
            asm volatile("tcgen05.ld.sync.aligned.32x32b.x4.b32 {%0,%1,%2,%3}, [%4];"
                         : "=r"(r0), "=r"(r1), "=r"(r2), "=r"(r3)
                         : "r"(tmem + t * 128 + s * 32 + cg * 4));
            asm volatile("tcgen05.wait::ld.sync.aligned;" ::: "memory");
            const int sh = 4 * (t + s);
            uint32_t rs[4] = {r0, r1, r2, r3};
#pragma unroll
            for (int c = 0; c < 4; c++) {
                int iv = (int)__uint_as_float(rs[c]);   // f32 accumulators hold exact integers
                iv = iv < -8192 ? -8192 : (iv > 8191 ? 8191 : iv);
                sum[c] += ((long long)iv) << sh;
            }
        }
#pragma unroll
        for (int c = 0; c < 4; c++) {
            float z = acm_finish(sum[c]);
            int nn = n0 + cg * 4 + c;
            int b2 = nn / (OH * OW);
            int r2 = nn - b2 * (OH * OW);
            int oh2 = r2 / OW, ow2 = r2 - oh2 * OW;
            outz[(((size_t)b2 * 512 + o) * OH + oh2) * OW + ow2] = z;
            if (zsl) {
                int qi = quant16(z);
                unsigned neg = qi < 0 ? 0x80u : 0u;
                int mag = qi < 0 ? -qi : qi;
                size_t plane = (size_t)B * (OH + 2) * (OW + 2) * 512;
                size_t base = (((size_t)(b2 * (OH + 2) + oh2 + 1)) * (OW + 2) + (ow2 + 1)) * 512 + o;
#pragma unroll
                for (int s2 = 0; s2 < 4; s2++) {
                    int m = (mag >> (4 * s2)) & 15;
                    unsigned long long sel = (m & 8) ? FP8LUT_HI : FP8LUT_LO;
                    unsigned byte = (unsigned)(sel >> ((m & 7) * 8)) & 0xFFu;
                    byte |= m ? neg : 0u;
                    *(uint8_t*)(zsl + s2 * plane + base) = (uint8_t)byte;
                }
            }
        }
    }

    __syncthreads();
    if (wid == 0)
        asm volatile("tcgen05.dealloc.cta_group::1.sync.aligned.b32 %0, %1;"
                     :: "r"(tmem), "r"(512u));
    // keep smem alive until every peer's multicasts / remote arrives are done
    asm volatile("barrier.cluster.arrive.aligned;" ::: "memory");
    asm volatile("barrier.cluster.wait.aligned;" ::: "memory");

#else
    // ================= legacy int8 mma.sync path (never executes on sm_103a) =================
    const int8_t* xs = (const int8_t*)xs_raw;
    const int8_t* ws = (const int8_t*)ws_raw;
    int8_t* zsl = (int8_t*)zsl_raw;

    const int n0 = blockIdx.x * 16;
    const int m0 = blockIdx.y * 64;
    const int warp = wid;
    const int wm = warp >> 1, wn = warp & 1;
    const int g = lane >> 2, tg = lane & 3;

    int8_t* sAb = (int8_t*)dsm;
    int8_t* sBb = (int8_t*)dsm + STAGES * 8192;

    const int4* wsv = (const int4*)ws;
    const int4* xsv = (const int4*)xs;

    const int aT = tid >> 6;
    const int aRow = tid & 63;
    const int aBase = (aT * 512 + m0 + aRow) * 288;
    const int aP0 = ((aRow >> 2) & 1) * 16;
    const uint32_t aDst0 = (uint32_t)__cvta_generic_to_shared(sAb) +
                           (uint32_t)((aT * 64 + aRow) * 32) + aP0;
    const uint32_t aDst1 = (uint32_t)__cvta_generic_to_shared(sAb) +
                           (uint32_t)((aT * 64 + aRow) * 32) + (16 - aP0);

    const int bS = tid >> 5;
    const int bPx = (tid >> 1) & 15;
    const int bHalf = tid & 1;
    int nn = n0 + bPx;
    int bb_ = nn / (OH * OW);
    int rr_ = nn - bb_ * OH * OW;
    int boh = rr_ / OW, bow = rr_ - boh * OW;
    const int bBase = (((bS * B + bb_) * IHP + 2 * boh) * IWP + 2 * bow) * 32;
    const uint32_t bDst = (uint32_t)__cvta_generic_to_shared(sBb) +
                          (uint32_t)((bS * 16 + bPx) * 32 + (bHalf ^ ((bPx >> 2) & 1)) * 16);

    int acc[4][4][4];
#pragma unroll
    for (int t = 0; t < 4; t++)
#pragma unroll
        for (int s = 0; s < 4; s++)
#pragma unroll
            for (int f = 0; f < 4; f++) acc[t][s][f] = 0;

    const int S = 144;

    auto load_stage = [&](int st, int buf) {
        int r = st >> 4, c = st & 15;
        int aoff = r * 32 + 2 * c;
        cp16(aDst0 + buf * 8192, wsv + aBase + aoff);
        cp16(aDst1 + buf * 8192, wsv + aBase + aoff + 1);
        if (tid < 128) {
            int kh = (r * 11) >> 5;
            int kw = r - 3 * kh;
            cp16(bDst + buf * 2048, xsv + bBase + (kh * IWP + kw) * 32 + 2 * c + bHalf);
        }
    };

#pragma unroll
    for (int ps = 0; ps < STAGES - 1; ps++) {
        load_stage(ps, ps);
        cp_commit();
    }

    const int off0 = ((g >> 2) & 1) * 16;
    const int off1 = 16 - off0;

#pragma unroll 1
    for (int i = 0; i < S; i++) {
        asm volatile("cp.async.wait_group 2;" ::: "memory");
        __syncthreads();

        const int buf = i & (STAGES - 1);
        const int8_t* Ap = sAb + buf * 8192;
        const int8_t* Bp = sBb + buf * 2048;

        int afr[4][4], bfr[4][2];
#pragma unroll
        for (int t = 0; t < 4; t++) {
            int rowb = (t * 64 + 16 * wm + g) * 32;
            afr[t][0] = *(const int*)(Ap + rowb + off0 + tg * 4);
            afr[t][1] = *(const int*)(Ap + rowb + 256 + off0 + tg * 4);
            afr[t][2] = *(const int*)(Ap + rowb + off1 + tg * 4);
            afr[t][3] = *(const int*)(Ap + rowb + 256 + off1 + tg * 4);
        }
#pragma unroll
        for (int s = 0; s < 4; s++) {
            int rowb = (s * 16 + 8 * wn + g) * 32;
            bfr[s][0] = *(const int*)(Bp + rowb + off0 + tg * 4);
            bfr[s][1] = *(const int*)(Bp + rowb + off1 + tg * 4);
        }
#pragma unroll
        for (int t = 0; t < 4; t++)
#pragma unroll
            for (int s = 0; s < 4; s++)
                mma_s8(acc[t][s], afr[t], bfr[s]);

        int nxt = i + STAGES - 1;
        if (nxt < S) load_stage(nxt, nxt & (STAGES - 1));
        cp_commit();
    }

#pragma unroll
    for (int fi = 0; fi < 4; fi++) {
        int row = 16 * wm + g + (fi >> 1) * 8;
        int col = 8 * wn + tg * 2 + (fi & 1);
        int o = m0 + row;
        int n2 = n0 + col;
        int b2 = n2 / (OH * OW);
        int r2 = n2 - b2 * OH * OW;
        int oh2 = r2 / OW, ow2 = r2 - oh2 * OW;
        int tmp[16];
#pragma unroll
        for (int t = 0; t < 4; t++)
#pragma unroll
            for (int s = 0; s < 4; s++) tmp[t * 4 + s] = acc[t][s][fi];
        float z = acm_combine16(tmp);
        outz[(((size_t)b2 * 512 + o) * OH + oh2) * OW + ow2] = z;
        if (zsl) {
            int qi = quant16(z);
            int sg = (qi > 0) - (qi < 0);
            int mag = qi < 0 ? -qi : qi;
            size_t plane = (size_t)B * (OH + 2) * (OW + 2) * 512;
            size_t base = (((size_t)(b2 * (OH + 2) + oh2 + 1)) * (OW + 2) + (ow2 + 1)) * 512 + o;
#pragma unroll
            for (int s2 = 0; s2 < 4; s2++)
                zsl[(size_t)s2 * plane + base] = (int8_t)(sg * ((mag >> (4 * s2)) & 15));
        }
    }
#endif
}

// ---------------- fused avgpool(6x6 of 8x8) + bit-sliced linear: [64,512]x[10,512] -> [64,10] ----------------
__global__ void linear_kernel(const float* __restrict__ wout, const int8_t* __restrict__ wsl,
                              float* __restrict__ outx) {
    int b = blockIdx.x;
    __shared__ int8_t sxs[4][512];
    int tid = threadIdx.x;  // 512 threads; tid = channel
    {
        const float* p = wout + ((size_t)(b * 512 + tid)) * 64;
        float s = 0.f;
#pragma unroll
        for (int i = 0; i < 6; i++)
#pragma unroll
            for (int j = 0; j < 6; j++) s += p[i * 8 + j];
        float pooled = s / 36.0f;
        int qi = quant16(pooled);
        int sg = (qi > 0) - (qi < 0);
        int mag = qi < 0 ? -qi : qi;
#pragma unroll
        for (int s2 = 0; s2 < 4; s2++) sxs[s2][tid] = (int8_t)(sg * ((mag >> (4 * s2)) & 15));
    }
    __syncthreads();
    int warp = tid >> 5, lane = tid & 31;
    if (warp < 10) {
        int o = warp;
        int acc[16];
#pragma unroll
        for (int i = 0; i < 16; i++) acc[i] = 0;
        for (int k = lane; k < 512; k += 32) {
            int xv[4];
#pragma unroll
            for (int s = 0; s < 4; s++) xv[s] = sxs[s][k];
#pragma unroll
            for (int t = 0; t < 4; t++) {
                int wv = wsl[(t * 10 + o) * 512 + k];
#pragma unroll
                for (int s = 0; s < 4; s++) acc[t * 4 + s] += wv * xv[s];
            }
        }
#pragma unroll
        for (int i = 0; i < 16; i++)
#pragma unroll
            for (int off = 16; off; off >>= 1)
                acc[i] += __shfl_xor_sync(0xffffffffu, acc[i], off);
        if (lane == 0) outx[b * 10 + o] = acm_combine16(acc);
    }
}

// ---------------- launch ----------------
extern "C" void kernel_launch(void* const* d_in, const int* in_sizes, int n_in,
                              void* d_out, int out_size) {
    const float* x    = (const float*)d_in[0];
    const float* w1   = (const float*)d_in[1];
    const float* w2   = (const float*)d_in[2];
    const float* w3   = (const float*)d_in[3];
    const float* wlin = (const float*)d_in[4];

    float* out  = (float*)d_out;
    float* outx = out;                                   // [64,10]
    float* outy = out + 640;                             // [64,512,32,32]
    float* outz = outy + (size_t)64 * 512 * 32 * 32;     // [64,512,16,16]
    float* outw = outz + (size_t)64 * 512 * 16 * 16;     // [64,512,8,8]

    void *p_xs, *p_zs, *p_w2, *p_w3, *p_wl;
    cudaGetSymbolAddress(&p_xs, g_xs2p);
    cudaGetSymbolAddress(&p_zs, g_zsp);
    cudaGetSymbolAddress(&p_w2, g_ws2);
    cudaGetSymbolAddress(&p_w3, g_ws3);
    cudaGetSymbolAddress(&p_wl, g_wslin);

    const int SMEM_DYN = 1024 + TSTG * 32768 + TSTG * 8192;  // 205824 B
    cudaFuncSetAttribute(mvm_conv_kernel, cudaFuncAttributeMaxDynamicSharedMemorySize, SMEM_DYN);

    // No memsets: device globals are zero-initialized and borders are never written.
    wprep_conv_kernel<<<(512 * 9 * 512 + 255) / 256, 256>>>(w2, p_w2);             // 1
    wprep_conv_kernel<<<(512 * 9 * 512 + 255) / 256, 256>>>(w3, p_w3);             // 2
    wprep_lin_kernel<<<20, 256>>>(wlin, (int8_t*)p_wl);                            // 3
    conv1_kernel<<<dim3(8, 32, 64), 256>>>(x, w1, outy, p_xs);                     // 4

    // 5: conv2 — tc tiles M=128 x N=32px: grid (512, 4)
    mvm_conv_kernel<<<dim3(512, 4), 256, SMEM_DYN>>>(p_xs, p_w2, outz, p_zs, 16, 16);

    // 6: conv3 — grid (128, 4)
    mvm_conv_kernel<<<dim3(128, 4), 256, SMEM_DYN>>>(p_zs, p_w3, outw, (void*)0, 8, 8);

    // 7: fused pool+linear
    linear_kernel<<<64, 512>>>(outw, (const int8_t*)p_wl, outx);
}

// round 17
// speedup vs baseline: 1.0672x; 1.0672x over previous
#include <cuda_runtime.h>
#include <cuda_bf16.h>
#include <cuda_fp8.h>
#include <cstdint>
#include <math.h>

#define BATCH 64
#define STAGES 4   // legacy path cp.async stages
#define CSZ 2      // tc path cluster size (A multicast; 148=2*74 packs perfectly)

// Arch-feature guard: tcgen05 only exists in the arch-specific (sm_103a/sm_100a) pass.
#if defined(__CUDA_ARCH__) && (defined(__CUDA_ARCH_FEAT_SM103_ALL) || defined(__CUDA_ARCH_FEAT_SM100_ALL))
#define HAS_TC 1
#else
#define HAS_TC 0
#endif

// ---------------- scratch (device globals; 1 byte/elem both paths: fp8 e4m3 | int8) ----------------
// NOTE: device globals are zero-initialized at module load. Kernels only ever write the
// interior pixels of the padded activation buffers, so the zero borders persist across
// all graph replays — no memsets needed.
__device__ __align__(1024) char g_xs2p[(size_t)4 * BATCH * 34 * 34 * 512]; // conv2 input slices
__device__ __align__(1024) char g_zsp [(size_t)4 * BATCH * 18 * 18 * 512]; // conv3 input slices
__device__ __align__(1024) char g_ws2 [(size_t)4 * 512 * 9 * 512];         // conv2 weight slices
__device__ __align__(1024) char g_ws3 [(size_t)4 * 512 * 9 * 512];         // conv3 weight slices
__device__ __align__(128) int8_t g_wslin[4 * 10 * 512];

// ---------------- helpers ----------------
__device__ __forceinline__ int quant16(float v) {
    float r = rintf(v * 16384.0f);
    r = fminf(fmaxf(r, -32768.0f), 32767.0f);
    return (int)r;
}

__device__ __forceinline__ float acm_finish(long long sum) {
    long long q = sum >> 4;
    int rem = (int)(sum & 15);
    if (rem > 8 || (rem == 8 && (q & 1))) q += 1;
    if (q >  2147483647LL) q =  2147483647LL;
    if (q < -2147483648LL) q = -2147483648LL;
    return (float)q * 5.9604644775390625e-08f;   // * 2^-24
}

__device__ __forceinline__ float acm_combine16(const int* acc) {
    long long sum = 0;
#pragma unroll
    for (int t = 0; t < 4; t++)
#pragma unroll
        for (int s = 0; s < 4; s++) {
            int v = acc[t * 4 + s];
            v = v < -8192 ? -8192 : (v > 8191 ? 8191 : v);
            sum += ((long long)v) << (4 * (t + s));
        }
    return acm_finish(sum);
}

__device__ __forceinline__ void cp16(uint32_t dst, const void* src) {
    asm volatile("cp.async.cg.shared.global [%0], [%1], 16;\n" :: "r"(dst), "l"(src));
}
__device__ __forceinline__ void cp_commit() {
    asm volatile("cp.async.commit_group;\n" ::: "memory");
}

__device__ __forceinline__ void mma_s8(int* d, const int* a, const int* b) {
    asm volatile(
        "mma.sync.aligned.m16n8k32.row.col.s32.s8.s8.s32 "
        "{%0,%1,%2,%3}, {%4,%5,%6,%7}, {%8,%9}, {%0,%1,%2,%3};\n"
        : "+r"(d[0]), "+r"(d[1]), "+r"(d[2]), "+r"(d[3])
        : "r"(a[0]), "r"(a[1]), "r"(a[2]), "r"(a[3]), "r"(b[0]), "r"(b[1]));
}

#if HAS_TC
__device__ __forceinline__ uint32_t elect_one() {
    uint32_t pred;
    asm volatile("{\n\t.reg .pred p;\n\telect.sync _|p, 0xFFFFFFFF;\n\tselp.b32 %0, 1, 0, p;\n\t}"
                 : "=r"(pred));
    return pred;
}
__device__ __forceinline__ void mbar_init(uint32_t addr, uint32_t cnt) {
    asm volatile("mbarrier.init.shared.b64 [%0], %1;" :: "r"(addr), "r"(cnt) : "memory");
}
__device__ __forceinline__ void mbar_wait(uint32_t mbar, uint32_t parity) {
    uint32_t done = 0;
    while (!done) {
        asm volatile(
            "{\n\t.reg .pred p;\n\t"
            "mbarrier.try_wait.parity.acquire.cta.shared::cta.b64 p, [%1], %2, 0x989680;\n\t"
            "selp.b32 %0, 1, 0, p;\n\t}"
            : "=r"(done) : "r"(mbar), "r"(parity) : "memory");
    }
}
// tcgen05 SS-mode fp8 (e4m3) mma, cg1, f32 accumulate, no block scales
__device__ __forceinline__ void tc_mma_f8(uint32_t d, uint64_t ad, uint64_t bd,
                                          uint32_t idesc, uint32_t en) {
    asm volatile(
        "{\n\t.reg .pred p;\n\t"
        "setp.ne.u32 p, %4, 0;\n\t"
        "tcgen05.mma.cta_group::1.kind::f8f6f4 [%0], %1, %2, %3, {%5,%5,%5,%5}, p;\n\t}"
        :: "r"(d), "l"(ad), "l"(bd), "r"(idesc), "r"(en), "r"(0u)
        : "memory");
}
// SW64 K-major smem descriptor base: layout=4, version=1, SBO=32 (512B = 8 rows x 64B), LBO=1
#define DESC64 ((4ULL << 61) | (1ULL << 46) | (32ULL << 32) | (1ULL << 16))
// idesc: dtype=F32 (1<<4), atype=E4M3, btype=E4M3, N=128 (16<<17), M=128 (8<<24)
#define MMA_IDESC_F8 0x08200010u
#endif

// ---------------- conv1: float conv 3->512 (3x3, s1, p1) + fused slice quantize ----------------
// (proven 148us version) Slice writes staged through smem -> 64B-contiguous u64 stores.
__global__ void conv1_kernel(const float* __restrict__ x, const float* __restrict__ w1,
                             float* __restrict__ y, void* __restrict__ xs_raw) {
    int h = blockIdx.y;
    int b = blockIdx.z;
    int o0 = blockIdx.x * 64;
    __shared__ float sx[3][3][34];
    __shared__ float sw[64 * 27];
    __shared__ unsigned long long stg[4][8][32];   // [s][o-group][w]
    int tid = threadIdx.x;
    for (int i = tid; i < 64 * 27; i += 256)
        sw[i] = w1[(o0 + i / 27) * 27 + (i % 27)];
    for (int i = tid; i < 306; i += 256) {
        int c = i / 102, rem = i % 102, dh = rem / 34, j = rem % 34;
        int ih = h - 1 + dh, iw = j - 1;
        float v = 0.f;
        if (ih >= 0 && ih < 32 && iw >= 0 && iw < 32)
            v = x[((b * 3 + c) * 32 + ih) * 32 + iw];
        sx[c][dh][j] = v;
    }
    __syncthreads();
    int w = tid & 31, og = tid >> 5;
    float acc[8];
#pragma unroll
    for (int i = 0; i < 8; i++) acc[i] = 0.f;
#pragma unroll
    for (int c = 0; c < 3; c++)
#pragma unroll
        for (int kh = 0; kh < 3; kh++)
#pragma unroll
            for (int kw = 0; kw < 3; kw++) {
                float xv = sx[c][kh][w + kw];
#pragma unroll
                for (int oo = 0; oo < 8; oo++)
                    acc[oo] += xv * sw[(og * 8 + oo) * 27 + c * 9 + kh * 3 + kw];
            }
    // y writes (coalesced across w within each warp)
#pragma unroll
    for (int oo = 0; oo < 8; oo++) {
        int o = o0 + og * 8 + oo;
        y[(((size_t)b * 512 + o) * 32 + h) * 32 + w] = acc[oo];
    }
    // pack 8 channel-bytes per plane into u64 and stage
    unsigned long long pk[4] = {0ull, 0ull, 0ull, 0ull};
#pragma unroll
    for (int oo = 0; oo < 8; oo++) {
        int qi = quant16(acc[oo]);
        int sg = (qi > 0) - (qi < 0);
        int mag = qi < 0 ? -qi : qi;
#pragma unroll
        for (int s = 0; s < 4; s++) {
            int v = sg * ((mag >> (4 * s)) & 15);
#if HAS_TC
            unsigned char byte = (unsigned char)__nv_cvt_float_to_fp8((float)v, __NV_SATFINITE, __NV_E4M3);
#else
            unsigned char byte = (unsigned char)(int8_t)v;
#endif
            pk[s] |= ((unsigned long long)byte) << (8 * oo);
        }
    }
#pragma unroll
    for (int s = 0; s < 4; s++) stg[s][og][w] = pk[s];
    __syncthreads();
    // write out: thread (ow = tid>>3, ogp = tid&7) -> 64B-contiguous runs per w
    int ow = tid >> 3, ogp = tid & 7;
    const size_t plane = (size_t)BATCH * 34 * 34 * 512;
    size_t pixbase = (((size_t)(b * 34 + h + 1)) * 34 + (ow + 1)) * 512 + o0 + ogp * 8;
    char* xs = (char*)xs_raw;
#pragma unroll
    for (int s = 0; s < 4; s++)
        *(unsigned long long*)(xs + s * plane + pixbase) = stg[s][ogp][ow];
}

// ---------------- weight prep (both conv layers in ONE launch; blockIdx.y selects tensor) ----------------
// tc path: blocked+preswizzled: [mt(4)][chunk(72)][row(512)=t*128+ol][64B], 32KB/chunk
// legacy : [t][o][r*512+c]
__global__ void wprep_conv_kernel(const float* __restrict__ wa, void* __restrict__ wsa_raw,
                                  const float* __restrict__ wb, void* __restrict__ wsb_raw) {
    int idx = blockIdx.x * blockDim.x + threadIdx.x;
    if (idx >= 512 * 9 * 512) return;
    const float* w = blockIdx.y ? wb : wa;
    void* ws_raw = blockIdx.y ? wsb_raw : wsa_raw;
    int c = idx & 511;
    int r = (idx >> 9) % 9;
    int o = idx / (512 * 9);
    float v = w[((size_t)o * 512 + c) * 9 + r];
    int qi = quant16(v);
    int sg = (qi > 0) - (qi < 0);
    int mag = qi < 0 ? -qi : qi;
#if HAS_TC
    __nv_fp8_e4m3* ws = (__nv_fp8_e4m3*)ws_raw;
    int mt = o >> 7, ol = o & 127;
    int chunk = r * 8 + (c >> 6);
    int j = (c >> 4) & 3;
    int byte = c & 15;
#pragma unroll
    for (int t = 0; t < 4; t++) {
        int row = t * 128 + ol;
        int sw = (row >> 1) & 3;
        size_t dst = (((size_t)(mt * 72 + chunk) * 512 + row) * 64) + ((j ^ sw) * 16) + byte;
        ws[dst] = __nv_fp8_e4m3((float)(sg * ((mag >> (4 * t)) & 15)));
    }
#else
    int8_t* ws = (int8_t*)ws_raw;
    size_t plane = (size_t)512 * 4608;
#pragma unroll
    for (int t = 0; t < 4; t++)
        ws[(size_t)t * plane + (size_t)o * 4608 + r * 512 + c] =
            (int8_t)(sg * ((mag >> (4 * t)) & 15));
#endif
}

__global__ void wprep_lin_kernel(const float* __restrict__ w, int8_t* __restrict__ ws) {
    int idx = blockIdx.x * blockDim.x + threadIdx.x;
    if (idx >= 10 * 512) return;
    int k = idx & 511, o = idx >> 9;
    int qi = quant16(w[o * 512 + k]);
    int sg = (qi > 0) - (qi < 0);
    int mag = qi < 0 ? -qi : qi;
#pragma unroll
    for (int t = 0; t < 4; t++)
        ws[(t * 10 + o) * 512 + k] = (int8_t)(sg * ((mag >> (4 * t)) & 15));
}

// ---------------- bit-sliced MVM conv: warp-specialized tcgen05 fp8 + A multicast | legacy ----------------
// tc grid: (N/32, 4). Legacy path never executes on sm_103a.
__global__ void __launch_bounds__(256, 1) __cluster_dims__(CSZ, 1, 1) mvm_conv_kernel(
    const void* __restrict__ xs_raw, const void* __restrict__ ws_raw,
    float* __restrict__ outz, void* __restrict__ zsl_raw, int OH, int OW) {

    extern __shared__ __align__(1024) char dsm[];
    const int B = BATCH;
    const int IHP = 2 * OH + 2, IWP = 2 * OW + 2;
    const int tid = threadIdx.x;
    const int lane = tid & 31, wid = tid >> 5;

#if HAS_TC
    // ================= tcgen05 fp8, warp-specialized producer/consumer =================
    // Accumulators: 4 TMEM regions (one per t-slice), each M=128 x N=128 where the
    // N index is s*32+px (B smem rows are s*32+px). A read once per (t,k): 32KB/chunk.
    const uint8_t* xs = (const uint8_t*)xs_raw;
    const uint8_t* ws = (const uint8_t*)ws_raw;
    __nv_fp8_e4m3* zsl = (__nv_fp8_e4m3*)zsl_raw;

    const int n0 = blockIdx.x * 32;
    const int mt = blockIdx.y;
    const int m0 = mt * 128;
    uint32_t rank;
    asm("mov.u32 %0, %%cluster_ctarank;" : "=r"(rank));

    const uint32_t sbase = (uint32_t)__cvta_generic_to_shared(dsm);
    const uint32_t mb_done  = sbase + 16;    // 4 x 8B, count 1 (mma commit)
    const uint32_t mb_full  = sbase + 48;    // 4 x 8B, count 129 (128 B-arrives + 1 A expect_tx)
    const uint32_t mb_empty = sbase + 80;    // 4 x 8B, count CSZ (cluster buf-free)
    const int OFF_A = 1024;                  // 4 x 32KB (512 rows x 64B, row = t*128+ol)
    const int OFF_B = 1024 + 131072;         // 4 x 8KB  (128 rows x 64B, row = s*32+px)

    if (tid == 0) {
#pragma unroll
        for (int i = 0; i < 4; i++) {
            mbar_init(mb_done  + i * 8, 1);
            mbar_init(mb_full  + i * 8, 129);
            mbar_init(mb_empty + i * 8, CSZ);
        }
    }
    __syncthreads();
    // all cluster CTAs' barriers initialized before any multicast targets them
    asm volatile("barrier.cluster.arrive.aligned;" ::: "memory");
    asm volatile("barrier.cluster.wait.aligned;" ::: "memory");

    uint32_t tmem = 0;

    if (wid == 0) {
        // ---------------- consumer warp ----------------
        asm volatile("tcgen05.alloc.cta_group::1.sync.aligned.shared::cta.b32 [%0], %1;"
                     :: "r"(sbase), "r"(512u) : "memory");
        asm volatile("ld.shared.b32 %0, [%1];" : "=r"(tmem) : "r"(sbase));

#pragma unroll 1
        for (int c = 0; c < 72; c++) {
            const int buf = c & 3;
            const uint32_t par = (uint32_t)((c >> 2) & 1);
            mbar_wait(mb_full + buf * 8, par);     // A (tx) + B (128 arrives) both done
            if (elect_one()) {
                asm volatile("fence.proxy.async.shared::cta;" ::: "memory");
                asm volatile("tcgen05.fence::after_thread_sync;" ::: "memory");
                uint64_t aD0 = DESC64 | (uint64_t)(((sbase + OFF_A + buf * 32768) >> 4) & 0x3FFF);
                uint64_t bD0 = DESC64 | (uint64_t)(((sbase + OFF_B + buf * 8192) >> 4) & 0x3FFF);
#pragma unroll
                for (int t = 0; t < 4; t++)
#pragma unroll
                    for (int k = 0; k < 2; k++) {   // K=32 fp8 per dispatch, N=128
                        uint64_t ad = aD0 + (uint64_t)(t * 512 + k * 2);
                        uint64_t bd = bD0 + (uint64_t)(k * 2);
                        uint32_t d = tmem + t * 128;
                        tc_mma_f8(d, ad, bd, MMA_IDESC_F8, (uint32_t)(c + k));
                    }
                asm volatile(
                    "tcgen05.commit.cta_group::1.mbarrier::arrive::one.shared::cluster.b64 [%0];"
                    :: "r"(mb_done + buf * 8) : "memory");
            }
        }
    } else if (tid >= 128) {
        // ---------------- producer warps (4..7) ----------------
        const int px = tid & 31;               // pixel within n-tile
        const int n = n0 + px;
        const int bb = n / (OH * OW);
        const int rr = n - bb * (OH * OW);
        const int oh = rr / OW, ow = rr - oh * OW;
        const size_t sPlane = (size_t)B * IHP * IWP * 512;
        const uint8_t* bsrc0 =
            xs + (size_t)((tid - 128) >> 5) * sPlane +
            ((size_t)(bb * IHP + 2 * oh) * IWP + 2 * ow) * 512;
        const uint32_t bdst0 = sbase + OFF_B + (tid - 128) * 64;
        const int bsw = (tid >> 1) & 3;

        auto fillA = [&](int c2) {
            const int buf2 = c2 & 3;
            const uint8_t* src = ws + ((size_t)(mt * 72 + c2) * 32768) + (size_t)rank * 16384;
            const uint32_t dst = sbase + OFF_A + buf2 * 32768 + rank * 16384;
            const uint32_t fb = mb_full + buf2 * 8;
            asm volatile("mbarrier.arrive.expect_tx.shared.b64 _, [%0], %1;"
                         :: "r"(fb), "r"(32768u) : "memory");
            asm volatile(
                "cp.async.bulk.shared::cluster.global.mbarrier::complete_tx::bytes.multicast::cluster "
                "[%0], [%1], %2, [%3], %4;"
                :: "r"(dst), "l"(src), "r"(16384u), "r"(fb), "h"((unsigned short)0x3)
                : "memory");
        };
        auto fillB = [&](int c2) {
            const int buf2 = c2 & 3;
            const int r = c2 >> 3, cc = c2 & 7;
            int kh = r / 3, kw = r - 3 * kh;
            const uint8_t* src = bsrc0 + (size_t)(kh * IWP + kw) * 512 + cc * 64;
            uint32_t dst = bdst0 + buf2 * 8192;
#pragma unroll
            for (int j = 0; j < 4; j++) cp16(dst + ((j ^ bsw) * 16), src + j * 16);
            // hardware arrival on full when this thread's prior cp.asyncs land
            asm volatile("cp.async.mbarrier.arrive.noinc.shared::cta.b64 [%0];"
                         :: "r"(mb_full + buf2 * 8) : "memory");
        };

        // prologue: stages 0..2
#pragma unroll
        for (int ps = 0; ps < 3; ps++) {
            if (tid == 128) fillA(ps);
            fillB(ps);
        }

#pragma unroll 1
        for (int c = 0; c < 72; c++) {
            if (c >= 1) {
                const int pb = (c - 1) & 3;
                const uint32_t pp = (uint32_t)(((c - 1) >> 2) & 1);
                mbar_wait(mb_done + pb * 8, pp);       // local mma(c-1) drained
                if (tid == 129) {                      // announce buf free to all peers
#pragma unroll
                    for (int pr = 0; pr < CSZ; pr++) {
                        asm volatile(
                            "{\n\t.reg .b32 ra;\n\t"
                            "mapa.shared::cluster.u32 ra, %0, %1;\n\t"
                            "mbarrier.arrive.shared::cluster.b64 _, [ra];\n\t}"
                            :: "r"(mb_empty + pb * 8), "r"(pr) : "memory");
                    }
                }
                if (tid == 128)
                    mbar_wait(mb_empty + pb * 8, pp);  // all cluster CTAs done with this buf
            }
            if (c + 3 < 72) {
                if (tid == 128) fillA(c + 3);
                fillB(c + 3);
            }
        }
    }
    // warps 1-3 idle until epilogue

    __syncthreads();
    // final mma completion: each done barrier's 18th (last) phase has parity 1
#pragma unroll
    for (int i = 0; i < 4; i++) mbar_wait(mb_done + i * 8, 1u);
    asm volatile("tcgen05.fence::after_thread_sync;" ::: "memory");
    asm volatile("ld.shared.b32 %0, [%1];" : "=r"(tmem) : "r"(sbase));

    // epilogue: warp w handles rows (w&3)*32+lane, col-groups (w>>2)*4 .. +3
    // acc(t,s,px) lives at TMEM col t*128 + s*32 + px
    const int o = m0 + (wid & 3) * 32 + lane;
    const int cg0 = (wid >> 2) * 4;
#pragma unroll 1
    for (int cgi = 0; cgi < 4; cgi++) {
        const int cg = cg0 + cgi;
        long long sum[4] = {0, 0, 0, 0};
#pragma unroll
        for (int ts = 0; ts < 16; ts++) {
            const int t = ts >> 2, s = ts & 3;
            uint32_t r0, r1, r2, r3;
            asm volatile("tcgen05.ld.sync.aligned.32x32b.x4.b32 {%0,%1,%2,%3}, [%4];"
                         : "=r"(r0), "=r"(r1), "=r"(r2), "=r"(r3)
                         : "r"(tmem + t * 128 + s * 32 + cg * 4));
            asm volatile("tcgen05.wait::ld.sync.aligned;" ::: "memory");
            const int sh = 4 * (t + s);
            uint32_t rs[4] = {r0, r1, r2, r3};
#pragma unroll
            for (int c = 0; c < 4; c++) {
                int iv = (int)__uint_as_float(rs[c]);   // f32 accumulators hold exact integers
                iv = iv < -8192 ? -8192 : (iv > 8191 ? 8191 : iv);
                sum[c] += ((long long)iv) << sh;
            }
        }
#pragma unroll
        for (int c = 0; c < 4; c++) {
            float z = acm_finish(sum[c]);
            int nn = n0 + cg * 4 + c;
            int b2 = nn / (OH * OW);
            int r2 = nn - b2 * (OH * OW);
            int oh2 = r2 / OW, ow2 = r2 - oh2 * OW;
            outz[(((size_t)b2 * 512 + o) * OH + oh2) * OW + ow2] = z;
            if (zsl) {
                int qi = quant16(z);
                int sg = (qi > 0) - (qi < 0);
                int mag = qi < 0 ? -qi : qi;
                size_t plane = (size_t)B * (OH + 2) * (OW + 2) * 512;
                size_t base = (((size_t)(b2 * (OH + 2) + oh2 + 1)) * (OW + 2) + (ow2 + 1)) * 512 + o;
#pragma unroll
                for (int s2 = 0; s2 < 4; s2++)
                    zsl[(size_t)s2 * plane + base] =
                        __nv_fp8_e4m3((float)(sg * ((mag >> (4 * s2)) & 15)));
            }
        }
    }

    __syncthreads();
    if (wid == 0)
        asm volatile("tcgen05.dealloc.cta_group::1.sync.aligned.b32 %0, %1;"
                     :: "r"(tmem), "r"(512u));
    // keep smem alive until every peer's multicasts / remote arrives are done
    asm volatile("barrier.cluster.arrive.aligned;" ::: "memory");
    asm volatile("barrier.cluster.wait.aligned;" ::: "memory");

#else
    // ================= legacy int8 mma.sync path (never executes on sm_103a) =================
    const int8_t* xs = (const int8_t*)xs_raw;
    const int8_t* ws = (const int8_t*)ws_raw;
    int8_t* zsl = (int8_t*)zsl_raw;

    const int n0 = blockIdx.x * 16;
    const int m0 = blockIdx.y * 64;
    const int warp = wid;
    const int wm = warp >> 1, wn = warp & 1;
    const int g = lane >> 2, tg = lane & 3;

    int8_t* sAb = (int8_t*)dsm;
    int8_t* sBb = (int8_t*)dsm + STAGES * 8192;

    const int4* wsv = (const int4*)ws;
    const int4* xsv = (const int4*)xs;

    const int aT = tid >> 6;
    const int aRow = tid & 63;
    const int aBase = (aT * 512 + m0 + aRow) * 288;
    const int aP0 = ((aRow >> 2) & 1) * 16;
    const uint32_t aDst0 = (uint32_t)__cvta_generic_to_shared(sAb) +
                           (uint32_t)((aT * 64 + aRow) * 32) + aP0;
    const uint32_t aDst1 = (uint32_t)__cvta_generic_to_shared(sAb) +
                           (uint32_t)((aT * 64 + aRow) * 32) + (16 - aP0);

    const int bS = tid >> 5;
    const int bPx = (tid >> 1) & 15;
    const int bHalf = tid & 1;
    int nn = n0 + bPx;
    int bb_ = nn / (OH * OW);
    int rr_ = nn - bb_ * OH * OW;
    int boh = rr_ / OW, bow = rr_ - boh * OW;
    const int bBase = (((bS * B + bb_) * IHP + 2 * boh) * IWP + 2 * bow) * 32;
    const uint32_t bDst = (uint32_t)__cvta_generic_to_shared(sBb) +
                          (uint32_t)((bS * 16 + bPx) * 32 + (bHalf ^ ((bPx >> 2) & 1)) * 16);

    int acc[4][4][4];
#pragma unroll
    for (int t = 0; t < 4; t++)
#pragma unroll
        for (int s = 0; s < 4; s++)
#pragma unroll
            for (int f = 0; f < 4; f++) acc[t][s][f] = 0;

    const int S = 144;

    auto load_stage = [&](int st, int buf) {
        int r = st >> 4, c = st & 15;
        int aoff = r * 32 + 2 * c;
        cp16(aDst0 + buf * 8192, wsv + aBase + aoff);
        cp16(aDst1 + buf * 8192, wsv + aBase + aoff + 1);
        if (tid < 128) {
            int kh = (r * 11) >> 5;
            int kw = r - 3 * kh;
            cp16(bDst + buf * 2048, xsv + bBase + (kh * IWP + kw) * 32 + 2 * c + bHalf);
        }
    };

#pragma unroll
    for (int ps = 0; ps < STAGES - 1; ps++) {
        load_stage(ps, ps);
        cp_commit();
    }

    const int off0 = ((g >> 2) & 1) * 16;
    const int off1 = 16 - off0;

#pragma unroll 1
    for (int i = 0; i < S; i++) {
        asm volatile("cp.async.wait_group 2;" ::: "memory");
        __syncthreads();

        const int buf = i & (STAGES - 1);
        const int8_t* Ap = sAb + buf * 8192;
        const int8_t* Bp = sBb + buf * 2048;

        int afr[4][4], bfr[4][2];
#pragma unroll
        for (int t = 0; t < 4; t++) {
            int rowb = (t * 64 + 16 * wm + g) * 32;
            afr[t][0] = *(const int*)(Ap + rowb + off0 + tg * 4);
            afr[t][1] = *(const int*)(Ap + rowb + 256 + off0 + tg * 4);
            afr[t][2] = *(const int*)(Ap + rowb + off1 + tg * 4);
            afr[t][3] = *(const int*)(Ap + rowb + 256 + off1 + tg * 4);
        }
#pragma unroll
        for (int s = 0; s < 4; s++) {
            int rowb = (s * 16 + 8 * wn + g) * 32;
            bfr[s][0] = *(const int*)(Bp + rowb + off0 + tg * 4);
            bfr[s][1] = *(const int*)(Bp + rowb + off1 + tg * 4);
        }
#pragma unroll
        for (int t = 0; t < 4; t++)
#pragma unroll
            for (int s = 0; s < 4; s++)
                mma_s8(acc[t][s], afr[t], bfr[s]);

        int nxt = i + STAGES - 1;
        if (nxt < S) load_stage(nxt, nxt & (STAGES - 1));
        cp_commit();
    }

#pragma unroll
    for (int fi = 0; fi < 4; fi++) {
        int row = 16 * wm + g + (fi >> 1) * 8;
        int col = 8 * wn + tg * 2 + (fi & 1);
        int o = m0 + row;
        int n2 = n0 + col;
        int b2 = n2 / (OH * OW);
        int r2 = n2 - b2 * OH * OW;
        int oh2 = r2 / OW, ow2 = r2 - oh2 * OW;
        int tmp[16];
#pragma unroll
        for (int t = 0; t < 4; t++)
#pragma unroll
            for (int s = 0; s < 4; s++) tmp[t * 4 + s] = acc[t][s][fi];
        float z = acm_combine16(tmp);
        outz[(((size_t)b2 * 512 + o) * OH + oh2) * OW + ow2] = z;
        if (zsl) {
            int qi = quant16(z);
            int sg = (qi > 0) - (qi < 0);
            int mag = qi < 0 ? -qi : qi;
            size_t plane = (size_t)B * (OH + 2) * (OW + 2) * 512;
            size_t base = (((size_t)(b2 * (OH + 2) + oh2 + 1)) * (OW + 2) + (ow2 + 1)) * 512 + o;
#pragma unroll
            for (int s2 = 0; s2 < 4; s2++)
                zsl[(size_t)s2 * plane + base] = (int8_t)(sg * ((mag >> (4 * s2)) & 15));
        }
    }
#endif
}

// ---------------- fused avgpool(6x6 of 8x8) + bit-sliced linear: [64,512]x[10,512] -> [64,10] ----------------
__global__ void linear_kernel(const float* __restrict__ wout, const int8_t* __restrict__ wsl,
                              float* __restrict__ outx) {
    int b = blockIdx.x;
    __shared__ int8_t sxs[4][512];
    int tid = threadIdx.x;  // 512 threads; tid = channel
    {
        const float* p = wout + ((size_t)(b * 512 + tid)) * 64;
        float s = 0.f;
#pragma unroll
        for (int i = 0; i < 6; i++)
#pragma unroll
            for (int j = 0; j < 6; j++) s += p[i * 8 + j];
        float pooled = s / 36.0f;
        int qi = quant16(pooled);
        int sg = (qi > 0) - (qi < 0);
        int mag = qi < 0 ? -qi : qi;
#pragma unroll
        for (int s2 = 0; s2 < 4; s2++) sxs[s2][tid] = (int8_t)(sg * ((mag >> (4 * s2)) & 15));
    }
    __syncthreads();
    int warp = tid >> 5, lane = tid & 31;
    if (warp < 10) {
        int o = warp;
        int acc[16];
#pragma unroll
        for (int i = 0; i < 16; i++) acc[i] = 0;
        for (int k = lane; k < 512; k += 32) {
            int xv[4];
#pragma unroll
            for (int s = 0; s < 4; s++) xv[s] = sxs[s][k];
#pragma unroll
            for (int t = 0; t < 4; t++) {
                int wv = wsl[(t * 10 + o) * 512 + k];
#pragma unroll
                for (int s = 0; s < 4; s++) acc[t * 4 + s] += wv * xv[s];
            }
        }
#pragma unroll
        for (int i = 0; i < 16; i++)
#pragma unroll
            for (int off = 16; off; off >>= 1)
                acc[i] += __shfl_xor_sync(0xffffffffu, acc[i], off);
        if (lane == 0) outx[b * 10 + o] = acm_combine16(acc);
    }
}

// ---------------- launch ----------------
extern "C" void kernel_launch(void* const* d_in, const int* in_sizes, int n_in,
                              void* d_out, int out_size) {
    const float* x    = (const float*)d_in[0];
    const float* w1   = (const float*)d_in[1];
    const float* w2   = (const float*)d_in[2];
    const float* w3   = (const float*)d_in[3];
    const float* wlin = (const float*)d_in[4];

    float* out  = (float*)d_out;
    float* outx = out;                                   // [64,10]
    float* outy = out + 640;                             // [64,512,32,32]
    float* outz = outy + (size_t)64 * 512 * 32 * 32;     // [64,512,16,16]
    float* outw = outz + (size_t)64 * 512 * 16 * 16;     // [64,512,8,8]

    void *p_xs, *p_zs, *p_w2, *p_w3, *p_wl;
    cudaGetSymbolAddress(&p_xs, g_xs2p);
    cudaGetSymbolAddress(&p_zs, g_zsp);
    cudaGetSymbolAddress(&p_w2, g_ws2);
    cudaGetSymbolAddress(&p_w3, g_ws3);
    cudaGetSymbolAddress(&p_wl, g_wslin);

    const int SMEM_DYN = 1024 + 4 * 32768 + 4 * 8192;  // 164864 B
    cudaFuncSetAttribute(mvm_conv_kernel, cudaFuncAttributeMaxDynamicSharedMemorySize, SMEM_DYN);

    // No memsets: device globals are zero-initialized and borders are never written.
    // 1: both conv weight preps in one launch (blockIdx.y selects tensor)
    wprep_conv_kernel<<<dim3((512 * 9 * 512 + 255) / 256, 2), 256>>>(w2, p_w2, w3, p_w3);
    wprep_lin_kernel<<<20, 256>>>(wlin, (int8_t*)p_wl);                            // 2
    conv1_kernel<<<dim3(8, 32, 64), 256>>>(x, w1, outy, p_xs);                     // 3

    // 4: conv2 — tc tiles M=128 x N=32px: grid (512, 4)
    mvm_conv_kernel<<<dim3(512, 4), 256, SMEM_DYN>>>(p_xs, p_w2, outz, p_zs, 16, 16);

    // 5: conv3 — grid (128, 4)
    mvm_conv_kernel<<<dim3(128, 4), 256, SMEM_DYN>>>(p_zs, p_w3, outw, (void*)0, 8, 8);

    // 6: fused pool+linear
    linear_kernel<<<64, 512>>>(outw, (const int8_t*)p_wl, outx);
}